// round 1
// baseline (speedup 1.0000x reference)
#include <cuda_runtime.h>
#include <cuda_bf16.h>
#include <stdint.h>

// Problem constants (fixed shapes for this problem)
#define B_ROWS 2048
#define RSZ    10
#define DIM    1024
#define NTGT   (B_ROWS * (RSZ - 1))   // 18432 targets
#define INV_TEMP 20.0f
#define ALPHA_C  1.0f
#define BETA_C   0.5f

// ---------------- device scratch (no allocation allowed) ----------------
__device__ __nv_bfloat16 g_an[(size_t)B_ROWS * DIM];   // normalized anchors (bf16)
__device__ __nv_bfloat16 g_tn[(size_t)NTGT * DIM];     // normalized targets (bf16)
__device__ float g_diag[B_ROWS];
__device__ float g_kl[B_ROWS];
__device__ float g_Z[B_ROWS];

__device__ __forceinline__ float warpReduceSum(float v) {
    v += __shfl_xor_sync(0xffffffffu, v, 16);
    v += __shfl_xor_sync(0xffffffffu, v, 8);
    v += __shfl_xor_sync(0xffffffffu, v, 4);
    v += __shfl_xor_sync(0xffffffffu, v, 2);
    v += __shfl_xor_sync(0xffffffffu, v, 1);
    return v;
}

__device__ __forceinline__ uint2 pack_bf16x4(float4 f) {
    __nv_bfloat162 lo = __floats2bfloat162_rn(f.x, f.y);
    __nv_bfloat162 hi = __floats2bfloat162_rn(f.z, f.w);
    uint2 u;
    u.x = *reinterpret_cast<unsigned int*>(&lo);
    u.y = *reinterpret_cast<unsigned int*>(&hi);
    return u;
}

// ---------------------------------------------------------------------------
// Kernel 1: per-group (b) normalize + KL term + diag + Z init.
// One block per b; 256 threads; each thread owns 4 contiguous floats per row.
// ---------------------------------------------------------------------------
__global__ void __launch_bounds__(256) prep_kernel(const float* __restrict__ emb,
                                                   const float* __restrict__ scores) {
    const int b    = blockIdx.x;
    const int tid  = threadIdx.x;
    const int lane = tid & 31;
    const int warp = tid >> 5;

    __shared__ float s_part[10][8];
    __shared__ float s_inv[10];
    __shared__ float s_cos[9];

    float4 v[RSZ];
    const float4* e4 = reinterpret_cast<const float4*>(emb) + (size_t)b * RSZ * (DIM / 4);
#pragma unroll
    for (int r = 0; r < RSZ; ++r) v[r] = e4[(size_t)r * (DIM / 4) + tid];

    // L2 norms of all 10 rows
#pragma unroll
    for (int r = 0; r < RSZ; ++r) {
        float p = v[r].x * v[r].x + v[r].y * v[r].y + v[r].z * v[r].z + v[r].w * v[r].w;
        p = warpReduceSum(p);
        if (lane == 0) s_part[r][warp] = p;
    }
    __syncthreads();
    if (tid < RSZ) {
        float ss = 0.f;
#pragma unroll
        for (int w = 0; w < 8; ++w) ss += s_part[tid][w];
        s_inv[tid] = 1.0f / fmaxf(sqrtf(ss), 1e-12f);
    }
    __syncthreads();

    // Write normalized bf16: anchor -> g_an[b], pos -> g_tn[b], negs -> g_tn[B + b*8 + k]
    const float inv0 = s_inv[0];
    {
        float4 a = v[0];
        a.x *= inv0; a.y *= inv0; a.z *= inv0; a.w *= inv0;
        reinterpret_cast<uint2*>(g_an + (size_t)b * DIM)[tid] = pack_bf16x4(a);
    }
#pragma unroll
    for (int r = 1; r < RSZ; ++r) {
        const float invr = s_inv[r];
        float4 t = v[r];
        t.x *= invr; t.y *= invr; t.z *= invr; t.w *= invr;
        size_t drow = (r == 1) ? (size_t)b
                               : (size_t)B_ROWS + (size_t)b * (RSZ - 2) + (size_t)(r - 2);
        reinterpret_cast<uint2*>(g_tn + drow * DIM)[tid] = pack_bf16x4(t);
    }

    // fp32 cosines anchor . row_r, r = 1..9
#pragma unroll
    for (int r = 1; r < RSZ; ++r) {
        float d = v[0].x * v[r].x + v[0].y * v[r].y + v[0].z * v[r].z + v[0].w * v[r].w;
        d = warpReduceSum(d);
        if (lane == 0) s_part[r - 1][warp] = d;
    }
    __syncthreads();
    if (tid < RSZ - 1) {
        float d = 0.f;
#pragma unroll
        for (int w = 0; w < 8; ++w) d += s_part[tid][w];
        s_cos[tid] = d * s_inv[0] * s_inv[tid + 1];
    }
    __syncthreads();

    if (tid == 0) {
        float rs[9], sc[9];
#pragma unroll
        for (int k = 0; k < 9; ++k) { rs[k] = s_cos[k]; sc[k] = scores[(size_t)b * 9 + k]; }
        float m1 = sc[0], m2 = rs[0];
#pragma unroll
        for (int k = 1; k < 9; ++k) { m1 = fmaxf(m1, sc[k]); m2 = fmaxf(m2, rs[k]); }
        float z1 = 0.f, z2 = 0.f;
#pragma unroll
        for (int k = 0; k < 9; ++k) { z1 += expf(sc[k] - m1); z2 += expf(rs[k] - m2); }
        const float lz1 = logf(z1), lz2 = logf(z2);
        float kl = 0.f;
#pragma unroll
        for (int k = 0; k < 9; ++k) {
            float lce = sc[k] - m1 - lz1;      // log ce_k
            float ce  = expf(lce);
            float lp  = rs[k] - m2 - lz2;      // log_p_k
            kl += ce * (lce - lp);
        }
        g_kl[b]   = kl / (float)(RSZ - 1);
        g_diag[b] = rs[0] * INV_TEMP;
        g_Z[b]    = 0.0f;                       // re-init every launch (graph-safe)
    }
}

// ---------------------------------------------------------------------------
// Kernel 2: fused GEMM (a_n @ t_n^T) + exp + row-sum into g_Z.
// 128x128 CTA tile, K=1024 loop in steps of 32. bf16 mma.sync m16n8k16.
// ---------------------------------------------------------------------------
#define LDS_BF16 40   // smem row stride in bf16 elems (80B, conflict-free for ldmatrix)

__device__ __forceinline__ void ldsm_x4(uint32_t addr, uint32_t* r) {
    asm volatile("ldmatrix.sync.aligned.m8n8.x4.shared.b16 {%0,%1,%2,%3}, [%4];"
                 : "=r"(r[0]), "=r"(r[1]), "=r"(r[2]), "=r"(r[3])
                 : "r"(addr));
}
__device__ __forceinline__ void mma_bf16(float* d, const uint32_t* a, uint32_t b0, uint32_t b1) {
    asm volatile(
        "mma.sync.aligned.m16n8k16.row.col.f32.bf16.bf16.f32 "
        "{%0,%1,%2,%3}, {%4,%5,%6,%7}, {%8,%9}, {%0,%1,%2,%3};"
        : "+f"(d[0]), "+f"(d[1]), "+f"(d[2]), "+f"(d[3])
        : "r"(a[0]), "r"(a[1]), "r"(a[2]), "r"(a[3]), "r"(b0), "r"(b1));
}

__global__ void __launch_bounds__(256, 2) gemm_z_kernel() {
    __shared__ __nv_bfloat16 sA[128 * LDS_BF16];
    __shared__ __nv_bfloat16 sB[128 * LDS_BF16];

    const int bn   = blockIdx.x;      // target tile (0..143)
    const int bm   = blockIdx.y;      // anchor tile (0..15)
    const int tid  = threadIdx.x;
    const int lane = tid & 31;
    const int warp = tid >> 5;
    const int wm   = warp & 3;        // 4 warps along M (32 rows each)
    const int wn   = warp >> 2;       // 2 warps along N (64 cols each)

    float acc[2][8][4];
#pragma unroll
    for (int i = 0; i < 2; ++i)
#pragma unroll
        for (int j = 0; j < 8; ++j)
#pragma unroll
            for (int c = 0; c < 4; ++c) acc[i][j][c] = 0.f;

    const uint4* gA = reinterpret_cast<const uint4*>(g_an);
    const uint4* gB = reinterpret_cast<const uint4*>(g_tn);
    uint4* s4A = reinterpret_cast<uint4*>(sA);
    uint4* s4B = reinterpret_cast<uint4*>(sB);
    const uint32_t baseA = (uint32_t)__cvta_generic_to_shared(sA);
    const uint32_t baseB = (uint32_t)__cvta_generic_to_shared(sB);

    // global->smem load pattern: each thread moves 2 x uint4 for A and B per K step
    const int row0 = tid >> 2;            // 0..63
    const int ch   = tid & 3;             // 16B chunk within 64B K-slice
    const int row1 = row0 + 64;
    const size_t gA0 = ((size_t)(bm * 128 + row0)) * 128 + ch;   // uint4 units, 128/row
    const size_t gA1 = ((size_t)(bm * 128 + row1)) * 128 + ch;
    const size_t gB0 = ((size_t)(bn * 128 + row0)) * 128 + ch;
    const size_t gB1 = ((size_t)(bn * 128 + row1)) * 128 + ch;
    const int sOff0 = row0 * 5 + ch;       // LDS_BF16/8 = 5 uint4 per row
    const int sOff1 = row1 * 5 + ch;

    uint4 ra0 = gA[gA0], ra1 = gA[gA1];
    uint4 rb0 = gB[gB0], rb1 = gB[gB1];

    for (int kt = 0; kt < 32; ++kt) {
        s4A[sOff0] = ra0; s4A[sOff1] = ra1;
        s4B[sOff0] = rb0; s4B[sOff1] = rb1;
        __syncthreads();

        if (kt < 31) {
            const size_t ko = (size_t)(kt + 1) * 4;
            ra0 = gA[gA0 + ko]; ra1 = gA[gA1 + ko];
            rb0 = gB[gB0 + ko]; rb1 = gB[gB1 + ko];
        }

#pragma unroll
        for (int kk = 0; kk < 2; ++kk) {
            uint32_t af[2][4], bf[4][4];
            const uint32_t byteoff = ((lane >> 4) << 4) + kk * 32;
#pragma unroll
            for (int mi = 0; mi < 2; ++mi) {
                uint32_t r = (uint32_t)(wm * 32 + mi * 16 + (lane & 15));
                ldsm_x4(baseA + r * 80u + byteoff, af[mi]);
            }
#pragma unroll
            for (int nt = 0; nt < 4; ++nt) {
                uint32_t r = (uint32_t)(wn * 64 + nt * 16 + (lane & 15));
                ldsm_x4(baseB + r * 80u + byteoff, bf[nt]);
            }
#pragma unroll
            for (int mi = 0; mi < 2; ++mi)
#pragma unroll
                for (int nt = 0; nt < 4; ++nt) {
                    mma_bf16(acc[mi][nt * 2 + 0], af[mi], bf[nt][0], bf[nt][2]);
                    mma_bf16(acc[mi][nt * 2 + 1], af[mi], bf[nt][1], bf[nt][3]);
                }
        }
        __syncthreads();
    }

    // Epilogue: exp(acc/temp), row-sum within warp tile, atomicAdd into g_Z.
#pragma unroll
    for (int mi = 0; mi < 2; ++mi) {
        float s0 = 0.f, s1 = 0.f;
#pragma unroll
        for (int ni = 0; ni < 8; ++ni) {
            s0 += __expf(acc[mi][ni][0] * INV_TEMP) + __expf(acc[mi][ni][1] * INV_TEMP);
            s1 += __expf(acc[mi][ni][2] * INV_TEMP) + __expf(acc[mi][ni][3] * INV_TEMP);
        }
        s0 += __shfl_xor_sync(0xffffffffu, s0, 1);
        s0 += __shfl_xor_sync(0xffffffffu, s0, 2);
        s1 += __shfl_xor_sync(0xffffffffu, s1, 1);
        s1 += __shfl_xor_sync(0xffffffffu, s1, 2);
        if ((lane & 3) == 0) {
            int r = bm * 128 + wm * 32 + mi * 16 + (lane >> 2);
            atomicAdd(&g_Z[r],     s0);
            atomicAdd(&g_Z[r + 8], s1);
        }
    }
}

// ---------------------------------------------------------------------------
// Kernel 3: final scalar reduction
// ---------------------------------------------------------------------------
__global__ void __launch_bounds__(256) finalize_kernel(float* __restrict__ out) {
    const int tid  = threadIdx.x;
    const int lane = tid & 31;
    const int warp = tid >> 5;
    __shared__ float skl[8], sce[8];

    float akl = 0.f, ace = 0.f;
    for (int b = tid; b < B_ROWS; b += 256) {
        akl += g_kl[b];
        ace += logf(g_Z[b]) - g_diag[b];
    }
    akl = warpReduceSum(akl);
    ace = warpReduceSum(ace);
    if (lane == 0) { skl[warp] = akl; sce[warp] = ace; }
    __syncthreads();
    if (tid == 0) {
        float k = 0.f, c = 0.f;
#pragma unroll
        for (int w = 0; w < 8; ++w) { k += skl[w]; c += sce[w]; }
        out[0] = BETA_C * (k / (float)B_ROWS) + ALPHA_C * (c / (float)B_ROWS);
    }
}

// ---------------------------------------------------------------------------
extern "C" void kernel_launch(void* const* d_in, const int* in_sizes, int n_in,
                              void* d_out, int out_size) {
    const float* emb    = (const float*)d_in[0];
    const float* scores = (const float*)d_in[1];
    // d_in[2] = row_sizes (all == R, constant) — unused

    prep_kernel<<<B_ROWS, 256>>>(emb, scores);
    dim3 grid(NTGT / 128, B_ROWS / 128);   // (144, 16)
    gemm_z_kernel<<<grid, 256>>>();
    finalize_kernel<<<1, 256>>>((float*)d_out);
}